// round 2
// baseline (speedup 1.0000x reference)
#include <cuda_runtime.h>
#include <math.h>

// Problem constants
#define Bsz 8192
#define Kc 32
#define Dd 256
#define TILE_B 32
#define NBLK (Bsz / TILE_B)   // 256 blocks
#define THREADS 512

// Shared memory layout (in floats)
//  xT   : [256 d][34]          (transposed X tile, pad 34 keeps 8B-aligned row pairs)
//  zs   : [32 r][256 d]
//  mus  : [32 r][256 d]
//  qs   : [32 r][256 d]        (q = exp(ls) + mu^2)
//  region C (union):
//    GEMM phase   : Wms[256][20], Wss[256][20]
//    cluster phase: iscT[64 d4][32 k] float4, mciT[64][32] float4
//  red  : redPi[16][32] + redG[16]
#define OFF_XT   0
#define OFF_ZS   8704
#define OFF_MU   16896
#define OFF_QS   25088
#define OFF_C    33280
#define OFF_WMS  33280
#define OFF_WSS  38400
#define OFF_ISCT 33280
#define OFF_MCIT 41472
#define OFF_REDP 49664
#define OFF_REDG 50176
#define SMEM_FLOATS 50192
#define SMEM_BYTES (SMEM_FLOATS * 4)

typedef unsigned long long u64;

// Device scratch (no allocation allowed in kernel_launch)
__device__ float g_isc[Kc * Dd];
__device__ float g_mci[Kc * Dd];
__device__ float g_c2[Kc];
__device__ float g_clsc[Kc];
__device__ float g_gaussPart[NBLK];
__device__ float g_piPart[NBLK * Kc];

// ---- packed f32x2 helpers (FFMA2 path: 2 MACs per issue slot) ----
__device__ __forceinline__ u64 pack2(float lo, float hi) {
    u64 r; asm("mov.b64 %0,{%1,%2};" : "=l"(r) : "f"(lo), "f"(hi)); return r;
}
__device__ __forceinline__ void unpack2(u64 v, float& lo, float& hi) {
    asm("mov.b64 {%0,%1},%2;" : "=f"(lo), "=f"(hi) : "l"(v));
}
__device__ __forceinline__ void fma2(u64& d, u64 a, u64 b) {
    asm("fma.rn.f32x2 %0,%1,%2,%0;" : "+l"(d) : "l"(a), "l"(b));
}
__device__ __forceinline__ u64 mul2(u64 a, u64 b) {
    u64 d; asm("mul.rn.f32x2 %0,%1,%2;" : "=l"(d) : "l"(a), "l"(b)); return d;
}

// ---------------------------------------------------------------------------
// Kernel 0: cluster-constant precompute
//   isc  = exp(-lsc)              [K,D]
//   mci  = mu_c * isc             [K,D]
//   c2   = sum_d mu_c^2 * isc     [K]
//   clsc = sum_d lsc              [K]
// ---------------------------------------------------------------------------
__global__ void prep_kernel(const float* __restrict__ mu_c,
                            const float* __restrict__ lsc) {
    int t = threadIdx.x;
    for (int i = t; i < Kc * Dd; i += 256) {
        float l = lsc[i];
        float iv = expf(-l);
        g_isc[i] = iv;
        g_mci[i] = mu_c[i] * iv;
    }
    if (t < Kc) {
        float c2 = 0.f, cl = 0.f;
        for (int d = 0; d < Dd; ++d) {
            float l = lsc[t * Dd + d];
            float iv = expf(-l);
            float mc = mu_c[t * Dd + d];
            c2 = fmaf(mc * mc, iv, c2);
            cl += l;
        }
        g_c2[t] = c2;
        g_clsc[t] = cl;
    }
}

// ---------------------------------------------------------------------------
// Kernel 1: fused per-32-row tile
//   Phase A: MU = X W_mu^T + b_mu, LS = X W_sig^T + b_sig  (smem-staged W)
//   Phase B: z = MU + sqrt(exp(LS))*eps  -> out, and zs/mus/qs to smem
//   Phase C: per-row K=32 cluster logits + softmax + loss partials (1 warp/2 rows)
// ---------------------------------------------------------------------------
__global__ void __launch_bounds__(THREADS)
fused_kernel(const float* __restrict__ X, const float* __restrict__ EPS,
             const float* __restrict__ Wmu, const float* __restrict__ bmu,
             const float* __restrict__ Wsig, const float* __restrict__ bsig,
             float* __restrict__ out) {
    extern __shared__ float sm[];
    float* xT   = sm + OFF_XT;
    float* zs   = sm + OFF_ZS;
    float* mus  = sm + OFF_MU;
    float* qs   = sm + OFF_QS;
    float* Wms  = sm + OFF_WMS;
    float* Wss  = sm + OFF_WSS;
    float4* iscT = (float4*)(sm + OFF_ISCT);
    float4* mciT = (float4*)(sm + OFF_MCIT);
    float* redPi = sm + OFF_REDP;
    float* redG  = sm + OFF_REDG;

    const int t = threadIdx.x;
    const int b0 = blockIdx.x * TILE_B;

    // ---- load X tile transposed: xT[d][r], pad-34 rows ----
    for (int i = t; i < TILE_B * Dd; i += THREADS) {
        int r = i >> 8, d = i & 255;
        xT[d * 34 + r] = X[(b0 + r) * Dd + d];
    }
    // first __syncthreads of the dc-loop covers this

    // ---- Phase A: dual GEMM, thread -> (col e, row-half h), 16 rows each ----
    const int e = t & 255;
    const int h = t >> 8;
    u64 amu[8], als[8];
#pragma unroll
    for (int j = 0; j < 8; ++j) { amu[j] = 0ull; als[j] = 0ull; }

    const float4* Wm4 = (const float4*)Wmu;
    const float4* Ws4 = (const float4*)Wsig;

    for (int dc = 0; dc < 16; ++dc) {           // 16 chunks of 16 d's
        __syncthreads();
        // coalesced global -> smem stage of W chunk (pad-20 rows, float4-safe)
#pragma unroll
        for (int pass = 0; pass < 2; ++pass) {
            int i = pass * THREADS + t;          // 0..1023 -> 1024 float4 per matrix
            int er = i >> 2, dd4 = i & 3;
            *(float4*)&Wms[er * 20 + dd4 * 4] = Wm4[er * 64 + dc * 4 + dd4];
            *(float4*)&Wss[er * 20 + dd4 * 4] = Ws4[er * 64 + dc * 4 + dd4];
        }
        __syncthreads();
#pragma unroll
        for (int dd4 = 0; dd4 < 4; ++dd4) {
            float4 wm = *(const float4*)&Wms[e * 20 + dd4 * 4];
            float4 ws = *(const float4*)&Wss[e * 20 + dd4 * 4];
#pragma unroll
            for (int q = 0; q < 4; ++q) {
                float wmv = (&wm.x)[q], wsv = (&ws.x)[q];
                u64 wm2 = pack2(wmv, wmv);
                u64 ws2 = pack2(wsv, wsv);
                int d = dc * 16 + dd4 * 4 + q;
                const u64* xp = (const u64*)&xT[d * 34 + h * 16];
#pragma unroll
                for (int j = 0; j < 8; ++j) {    // 8 row-pairs
                    u64 x2 = xp[j];
                    fma2(amu[j], x2, wm2);
                    fma2(als[j], x2, ws2);
                }
            }
        }
    }

    // ---- Phase B: bias, reparameterize, write z, stash row vectors ----
    {
        float bm = bmu[e], bs = bsig[e];
#pragma unroll
        for (int j = 0; j < 8; ++j) {
            float m0, m1, l0, l1;
            unpack2(amu[j], m0, m1);
            unpack2(als[j], l0, l1);
            int r0 = h * 16 + 2 * j;
#pragma unroll
            for (int s = 0; s < 2; ++s) {
                float mu = (s ? m1 : m0) + bm;
                float ls = (s ? l1 : l0) + bs;
                int r = r0 + s;
                float ez = __expf(ls);
                float ep = EPS[(b0 + r) * Dd + e];
                float z = fmaf(sqrtf(ez), ep, mu);
                out[(b0 + r) * Dd + e] = z;
                zs[r * Dd + e]  = z;
                mus[r * Dd + e] = mu;
                qs[r * Dd + e]  = fmaf(mu, mu, ez);
            }
        }
    }
    __syncthreads();

    // ---- load transposed cluster tables into region C (reuses W stage) ----
    for (int i = t; i < 2048; i += THREADS) {
        int d4 = i >> 5, k = i & 31;
        iscT[i] = *(const float4*)&g_isc[k * Dd + d4 * 4];
        mciT[i] = *(const float4*)&g_mci[k * Dd + d4 * 4];
    }
    __syncthreads();

    // ---- Phase C: one warp per 2 rows, lane == cluster k ----
    const int w = t >> 5, lane = t & 31;
    float c2v = g_c2[lane], clv = g_clsc[lane];
    float piAcc = 0.f, gAcc = 0.f;
#pragma unroll
    for (int rr = 0; rr < 2; ++rr) {
        int r = w * 2 + rr;
        u64 A1 = 0ull, A2 = 0ull, A3 = 0ull, A4 = 0ull;
        const u64* zp = (const u64*)&zs[r * Dd];
        const u64* mp = (const u64*)&mus[r * Dd];
        const u64* qp = (const u64*)&qs[r * Dd];
#pragma unroll 4
        for (int d4 = 0; d4 < 64; ++d4) {
            float4 iv = iscT[d4 * 32 + lane];
            float4 mv = mciT[d4 * 32 + lane];
            u64 ivA = pack2(iv.x, iv.y), ivB = pack2(iv.z, iv.w);
            u64 mvA = pack2(mv.x, mv.y), mvB = pack2(mv.z, mv.w);
            u64 zA = zp[2 * d4], zB = zp[2 * d4 + 1];
            u64 mA = mp[2 * d4], mB = mp[2 * d4 + 1];
            u64 qA = qp[2 * d4], qB = qp[2 * d4 + 1];
            fma2(A1, mul2(zA, zA), ivA); fma2(A1, mul2(zB, zB), ivB);
            fma2(A2, zA, mvA);           fma2(A2, zB, mvB);
            fma2(A3, qA, ivA);           fma2(A3, qB, ivB);
            fma2(A4, mA, mvA);           fma2(A4, mB, mvB);
        }
        float x0, x1;
        unpack2(A1, x0, x1); float a1 = x0 + x1;   // dot(z^2, isc_k)
        unpack2(A2, x0, x1); float a2 = x0 + x1;   // dot(z,   mci_k)
        unpack2(A3, x0, x1); float a3 = x0 + x1;   // dot(ez+mu^2, isc_k)
        unpack2(A4, x0, x1); float a4 = x0 + x1;   // dot(mu,  mci_k)

        float logit = -(a1 - 2.f * a2 + c2v);
        float S = clv + a3 - 2.f * a4 + c2v;

        // softmax over k (lanes)
        float mx = logit;
#pragma unroll
        for (int o = 16; o; o >>= 1) mx = fmaxf(mx, __shfl_xor_sync(0xffffffffu, mx, o));
        float p = __expf(logit - mx);
        float ssum = p;
#pragma unroll
        for (int o = 16; o; o >>= 1) ssum += __shfl_xor_sync(0xffffffffu, ssum, o);
        float pi = p / ssum + 1e-10f;

        piAcc += pi;
        float gs = pi * S;
#pragma unroll
        for (int o = 16; o; o >>= 1) gs += __shfl_xor_sync(0xffffffffu, gs, o);
        gAcc += gs;   // identical on all lanes after reduce
    }

    // ---- block-level partials (deterministic order) ----
    redPi[w * 32 + lane] = piAcc;
    if (lane == 0) redG[w] = gAcc;
    __syncthreads();
    if (w == 0) {
        float ps = 0.f;
#pragma unroll
        for (int i = 0; i < 16; ++i) ps += redPi[i * 32 + lane];
        g_piPart[blockIdx.x * 32 + lane] = ps;
        if (lane == 0) {
            float gsum = 0.f;
#pragma unroll
            for (int i = 0; i < 16; ++i) gsum += redG[i];
            g_gaussPart[blockIdx.x] = gsum;
        }
    }
}

// ---------------------------------------------------------------------------
// Kernel 2: final scalar reductions (256 threads, deterministic)
// ---------------------------------------------------------------------------
__global__ void finalize_kernel(float* __restrict__ out, int out_size) {
    __shared__ float sg[8];
    __shared__ float sp[8][32];
    int t = threadIdx.x;
    int lane = t & 31, w = t >> 5;

    // gaussian loss: 256 partials, one per thread
    float g = g_gaussPart[t];
#pragma unroll
    for (int o = 16; o; o >>= 1) g += __shfl_xor_sync(0xffffffffu, g, o);
    if (lane == 0) sg[w] = g;

    // pi sums: (w = block-chunk, lane = k)
    float ps = 0.f;
    for (int j = 0; j < 32; ++j) ps += g_piPart[(w * 32 + j) * 32 + lane];
    sp[w][lane] = ps;
    __syncthreads();

    if (t == 0) {
        float G = 0.f;
        for (int i = 0; i < 8; ++i) G += sg[i];
        out[out_size - 2] = 0.5f * G;
    }
    if (w == 0) {
        float P = 0.f;
        for (int i = 0; i < 8; ++i) P += sp[i][lane];
        float mp = P / (float)Bsz;
        float u = mp * logf(mp);
#pragma unroll
        for (int o = 16; o; o >>= 1) u += __shfl_xor_sync(0xffffffffu, u, o);
        if (lane == 0) out[out_size - 1] = u / (float)Kc;
    }
}

// ---------------------------------------------------------------------------
extern "C" void kernel_launch(void* const* d_in, const int* in_sizes, int n_in,
                              void* d_out, int out_size) {
    const float* X    = (const float*)d_in[0];  // embedded_state [B,1,D]
    const float* EPS  = (const float*)d_in[1];  // eps            [B,1,D]
    const float* Wmu  = (const float*)d_in[2];  // W_mu           [D,D]
    const float* bmu  = (const float*)d_in[3];  // b_mu           [D]
    const float* Wsig = (const float*)d_in[4];  // W_sig          [D,D]
    const float* bsig = (const float*)d_in[5];  // b_sig          [D]
    const float* muc  = (const float*)d_in[6];  // mu_c           [K,D]
    const float* lsc  = (const float*)d_in[7];  // log_sigma_sq_c [K,D]
    float* out = (float*)d_out;

    cudaFuncSetAttribute(fused_kernel,
                         cudaFuncAttributeMaxDynamicSharedMemorySize, SMEM_BYTES);

    prep_kernel<<<1, 256>>>(muc, lsc);
    fused_kernel<<<NBLK, THREADS, SMEM_BYTES>>>(X, EPS, Wmu, bmu, Wsig, bsig, out);
    finalize_kernel<<<1, 256>>>(out, out_size);
}

// round 3
// speedup vs baseline: 1.2423x; 1.2423x over previous
#include <cuda_runtime.h>
#include <math.h>

// Problem constants
#define Bsz 8192
#define Kc 32
#define Dd 256
#define TILE_B 32
#define NBLK (Bsz / TILE_B)   // 256 blocks
#define THREADS 512

// Shared memory layout (floats)
//  xP   [16 rp][256 d][2]  : interleaved row-pairs of X tile      (8192)
//  zs   [32 r][256 d]                                             (8192)
//  mus  [32 r][256 d]                                             (8192)
//  qs   [32 r][256 d]      : q = exp(ls) + mu^2                   (8192)
//  region C (union, 16384 floats):
//    GEMM:    WTm[16 d][256 e] (4096) + WTs[16 d][256 e] (4096)
//    cluster: iscT float4[64][32] (8192) + mciT float4[64][32] (8192)
//  red: redPi[16][32] (512) + redG[16]
#define OFF_XP   0
#define OFF_ZS   8192
#define OFF_MU   16384
#define OFF_QS   24576
#define OFF_C    32768
#define OFF_WTM  32768
#define OFF_WTS  36864
#define OFF_ISCT 32768
#define OFF_MCIT 40960
#define OFF_REDP 49152
#define OFF_REDG 49664
#define SMEM_FLOATS 49680
#define SMEM_BYTES (SMEM_FLOATS * 4)

typedef unsigned long long u64;

// Device scratch
__device__ float g_isc[Kc * Dd];
__device__ float g_mci[Kc * Dd];
__device__ float g_c2[Kc];
__device__ float g_clsc[Kc];
__device__ float g_gaussPart[NBLK];
__device__ float g_piPart[NBLK * Kc];

// ---- packed f32x2 helpers ----
__device__ __forceinline__ u64 pack2(float lo, float hi) {
    u64 r; asm("mov.b64 %0,{%1,%2};" : "=l"(r) : "f"(lo), "f"(hi)); return r;
}
__device__ __forceinline__ void unpack2(u64 v, float& lo, float& hi) {
    asm("mov.b64 {%0,%1},%2;" : "=f"(lo), "=f"(hi) : "l"(v));
}
__device__ __forceinline__ void fma2(u64& d, u64 a, u64 b) {
    asm("fma.rn.f32x2 %0,%1,%2,%0;" : "+l"(d) : "l"(a), "l"(b));
}
__device__ __forceinline__ u64 mul2(u64 a, u64 b) {
    u64 d; asm("mul.rn.f32x2 %0,%1,%2;" : "=l"(d) : "l"(a), "l"(b)); return d;
}

// ---------------------------------------------------------------------------
// Kernel 0: cluster-constant precompute (one warp per cluster k)
// ---------------------------------------------------------------------------
__global__ void __launch_bounds__(1024) prep_kernel(const float* __restrict__ mu_c,
                                                    const float* __restrict__ lsc) {
    int k = threadIdx.x >> 5, lane = threadIdx.x & 31;
    float c2 = 0.f, cl = 0.f;
#pragma unroll
    for (int j = 0; j < 8; ++j) {
        int d = j * 32 + lane;
        int i = k * Dd + d;
        float l = lsc[i];
        float iv = expf(-l);
        float mc = mu_c[i];
        g_isc[i] = iv;
        g_mci[i] = mc * iv;
        c2 = fmaf(mc * mc, iv, c2);
        cl += l;
    }
#pragma unroll
    for (int o = 16; o; o >>= 1) {
        c2 += __shfl_xor_sync(0xffffffffu, c2, o);
        cl += __shfl_xor_sync(0xffffffffu, cl, o);
    }
    if (lane == 0) { g_c2[k] = c2; g_clsc[k] = cl; }
}

// ---------------------------------------------------------------------------
// Kernel 1: fused per-32-row tile
// ---------------------------------------------------------------------------
__global__ void __launch_bounds__(THREADS)
fused_kernel(const float* __restrict__ X, const float* __restrict__ EPS,
             const float* __restrict__ Wmu, const float* __restrict__ bmu,
             const float* __restrict__ Wsig, const float* __restrict__ bsig,
             float* __restrict__ out) {
    extern __shared__ float sm[];
    float* xP  = sm + OFF_XP;
    float* zs  = sm + OFF_ZS;
    float* mus = sm + OFF_MU;
    float* qs  = sm + OFF_QS;
    float* WTm = sm + OFF_WTM;
    float* WTs = sm + OFF_WTS;
    float4* iscT = (float4*)(sm + OFF_ISCT);
    float4* mciT = (float4*)(sm + OFF_MCIT);
    float* redPi = sm + OFF_REDP;
    float* redG  = sm + OFF_REDG;

    const int t = threadIdx.x;
    const int b0 = blockIdx.x * TILE_B;
    const int wi = t >> 5, lane = t & 31;
    const int rowgrp = wi >> 2;              // 0..3 -> rows rowgrp*8..+7
    const int colquad = wi & 3;              // e0 = (colquad*32+lane)*2
    const int e0 = (colquad * 32 + lane) * 2;

    // ---- load X tile into interleaved row-pair layout xP[rp][d][2] ----
#pragma unroll
    for (int p = 0; p < 16; ++p) {
        int i = p * THREADS + t;
        int r = i >> 8, d = i & 255;
        xP[(r >> 1) * 512 + d * 2 + (r & 1)] = X[(b0 + r) * Dd + d];
    }

    // ---- prefetch pointer setup (per-pass (mat, e, j) decomposition) ----
    // pass p covers global float4 index g = p*512 + t of the chunk:
    //   m = g>>10 (0:mu 1:sig), rr = g&1023, j = rr&3 (d-sub f4), e = rr>>2
    const float4* pfsrc[4];
    float* dstPtr[4];
#pragma unroll
    for (int p = 0; p < 4; ++p) {
        int g = p * THREADS + t;
        int m = g >> 10;
        int rr = g & 1023;
        int j = rr & 3;
        int e = rr >> 2;
        const float* src = m ? Wsig : Wmu;
        pfsrc[p] = (const float4*)(src + e * Dd) + j;   // + chunk*4 float4 later
        float* dst = m ? WTs : WTm;
        dstPtr[p] = dst + (j * 4) * 256 + e;            // + c*256 per component
    }

    u64 acc[4][2][2];   // [row-pair][mat][col]
#pragma unroll
    for (int rp = 0; rp < 4; ++rp)
#pragma unroll
        for (int m = 0; m < 2; ++m) { acc[rp][m][0] = 0ull; acc[rp][m][1] = 0ull; }

    float4 pf[4];
#pragma unroll
    for (int p = 0; p < 4; ++p) pf[p] = pfsrc[p][0];

    // ---- Phase A: dual GEMM over 16 chunks of 16 d ----
    for (int ch = 0; ch < 16; ++ch) {
        __syncthreads();
#pragma unroll
        for (int p = 0; p < 4; ++p) {
            dstPtr[p][0]       = pf[p].x;
            dstPtr[p][256]     = pf[p].y;
            dstPtr[p][512]     = pf[p].z;
            dstPtr[p][768]     = pf[p].w;
        }
        __syncthreads();
        if (ch < 15) {
#pragma unroll
            for (int p = 0; p < 4; ++p) pf[p] = pfsrc[p][(ch + 1) * 4];
        }
        const int dg0 = ch * 16;
#pragma unroll
        for (int dd = 0; dd < 8; ++dd) {
            int d = dd * 2;
            float2 wmA = *(const float2*)&WTm[d * 256 + e0];
            float2 wmB = *(const float2*)&WTm[(d + 1) * 256 + e0];
            float2 wsA = *(const float2*)&WTs[d * 256 + e0];
            float2 wsB = *(const float2*)&WTs[(d + 1) * 256 + e0];
            u64 m0A = pack2(wmA.x, wmA.x), m1A = pack2(wmA.y, wmA.y);
            u64 m0B = pack2(wmB.x, wmB.x), m1B = pack2(wmB.y, wmB.y);
            u64 s0A = pack2(wsA.x, wsA.x), s1A = pack2(wsA.y, wsA.y);
            u64 s0B = pack2(wsB.x, wsB.x), s1B = pack2(wsB.y, wsB.y);
#pragma unroll
            for (int rp = 0; rp < 4; ++rp) {
                ulonglong2 xv = *(const ulonglong2*)&xP[(rowgrp * 4 + rp) * 512 + (dg0 + d) * 2];
                fma2(acc[rp][0][0], xv.x, m0A); fma2(acc[rp][0][1], xv.x, m1A);
                fma2(acc[rp][1][0], xv.x, s0A); fma2(acc[rp][1][1], xv.x, s1A);
                fma2(acc[rp][0][0], xv.y, m0B); fma2(acc[rp][0][1], xv.y, m1B);
                fma2(acc[rp][1][0], xv.y, s0B); fma2(acc[rp][1][1], xv.y, s1B);
            }
        }
    }

    // ---- Phase B: bias, reparameterize, write z, stash row vectors ----
    {
        float2 bm = *(const float2*)&bmu[e0];
        float2 bs = *(const float2*)&bsig[e0];
#pragma unroll
        for (int rp = 0; rp < 4; ++rp) {
            float mu0l, mu0h, mu1l, mu1h, ls0l, ls0h, ls1l, ls1h;
            unpack2(acc[rp][0][0], mu0l, mu0h);
            unpack2(acc[rp][0][1], mu1l, mu1h);
            unpack2(acc[rp][1][0], ls0l, ls0h);
            unpack2(acc[rp][1][1], ls1l, ls1h);
#pragma unroll
            for (int s = 0; s < 2; ++s) {
                int r = rowgrp * 8 + rp * 2 + s;
                float mu0 = (s ? mu0h : mu0l) + bm.x;
                float mu1 = (s ? mu1h : mu1l) + bm.y;
                float ls0 = (s ? ls0h : ls0l) + bs.x;
                float ls1 = (s ? ls1h : ls1l) + bs.y;
                float ez0 = __expf(ls0), ez1 = __expf(ls1);
                float2 ep = *(const float2*)&EPS[(b0 + r) * Dd + e0];
                float z0 = fmaf(sqrtf(ez0), ep.x, mu0);
                float z1 = fmaf(sqrtf(ez1), ep.y, mu1);
                float2 zv = {z0, z1};
                *(float2*)&out[(b0 + r) * Dd + e0] = zv;
                *(float2*)&zs[r * Dd + e0] = zv;
                float2 mv = {mu0, mu1};
                *(float2*)&mus[r * Dd + e0] = mv;
                float2 qv = {fmaf(mu0, mu0, ez0), fmaf(mu1, mu1, ez1)};
                *(float2*)&qs[r * Dd + e0] = qv;
            }
        }
    }
    __syncthreads();   // GEMM done everywhere; safe to overwrite region C

    // ---- load transposed cluster tables into region C ----
    for (int i = t; i < 2048; i += THREADS) {
        int d4 = i >> 5, k = i & 31;
        iscT[i] = *(const float4*)&g_isc[k * Dd + d4 * 4];
        mciT[i] = *(const float4*)&g_mci[k * Dd + d4 * 4];
    }
    __syncthreads();

    // ---- Phase C: one warp per 2 rows, lane == cluster k ----
    float c2v = g_c2[lane], clv = g_clsc[lane];
    float piAcc = 0.f, gAcc = 0.f;
#pragma unroll
    for (int rr = 0; rr < 2; ++rr) {
        int r = wi * 2 + rr;
        u64 A1 = 0ull, A2 = 0ull, A3 = 0ull, A4 = 0ull;
        const u64* zp = (const u64*)&zs[r * Dd];
        const u64* mp = (const u64*)&mus[r * Dd];
        const u64* qp = (const u64*)&qs[r * Dd];
#pragma unroll 4
        for (int d4 = 0; d4 < 64; ++d4) {
            float4 iv = iscT[d4 * 32 + lane];
            float4 mv = mciT[d4 * 32 + lane];
            u64 ivA = pack2(iv.x, iv.y), ivB = pack2(iv.z, iv.w);
            u64 mvA = pack2(mv.x, mv.y), mvB = pack2(mv.z, mv.w);
            u64 zA = zp[2 * d4], zB = zp[2 * d4 + 1];
            u64 mA = mp[2 * d4], mB = mp[2 * d4 + 1];
            u64 qA = qp[2 * d4], qB = qp[2 * d4 + 1];
            fma2(A1, mul2(zA, zA), ivA); fma2(A1, mul2(zB, zB), ivB);
            fma2(A2, zA, mvA);           fma2(A2, zB, mvB);
            fma2(A3, qA, ivA);           fma2(A3, qB, ivB);
            fma2(A4, mA, mvA);           fma2(A4, mB, mvB);
        }
        float x0, x1;
        unpack2(A1, x0, x1); float a1 = x0 + x1;
        unpack2(A2, x0, x1); float a2 = x0 + x1;
        unpack2(A3, x0, x1); float a3 = x0 + x1;
        unpack2(A4, x0, x1); float a4 = x0 + x1;

        float logit = -(a1 - 2.f * a2 + c2v);
        float S = clv + a3 - 2.f * a4 + c2v;

        float mx = logit;
#pragma unroll
        for (int o = 16; o; o >>= 1) mx = fmaxf(mx, __shfl_xor_sync(0xffffffffu, mx, o));
        float p = __expf(logit - mx);
        float ssum = p;
#pragma unroll
        for (int o = 16; o; o >>= 1) ssum += __shfl_xor_sync(0xffffffffu, ssum, o);
        float pi = p / ssum + 1e-10f;

        piAcc += pi;
        float gs = pi * S;
#pragma unroll
        for (int o = 16; o; o >>= 1) gs += __shfl_xor_sync(0xffffffffu, gs, o);
        gAcc += gs;
    }

    // ---- block-level partials ----
    redPi[wi * 32 + lane] = piAcc;
    if (lane == 0) redG[wi] = gAcc;
    __syncthreads();
    if (wi == 0) {
        float ps = 0.f;
#pragma unroll
        for (int i = 0; i < 16; ++i) ps += redPi[i * 32 + lane];
        g_piPart[blockIdx.x * 32 + lane] = ps;
        if (lane == 0) {
            float gsum = 0.f;
#pragma unroll
            for (int i = 0; i < 16; ++i) gsum += redG[i];
            g_gaussPart[blockIdx.x] = gsum;
        }
    }
}

// ---------------------------------------------------------------------------
// Kernel 2: final scalar reductions
// ---------------------------------------------------------------------------
__global__ void finalize_kernel(float* __restrict__ out, int out_size) {
    __shared__ float sg[8];
    __shared__ float sp[8][32];
    int t = threadIdx.x;
    int lane = t & 31, w = t >> 5;

    float g = g_gaussPart[t];
#pragma unroll
    for (int o = 16; o; o >>= 1) g += __shfl_xor_sync(0xffffffffu, g, o);
    if (lane == 0) sg[w] = g;

    float ps = 0.f;
    for (int j = 0; j < 32; ++j) ps += g_piPart[(w * 32 + j) * 32 + lane];
    sp[w][lane] = ps;
    __syncthreads();

    if (t == 0) {
        float G = 0.f;
        for (int i = 0; i < 8; ++i) G += sg[i];
        out[out_size - 2] = 0.5f * G;
    }
    if (w == 0) {
        float P = 0.f;
        for (int i = 0; i < 8; ++i) P += sp[i][lane];
        float mp = P / (float)Bsz;
        float u = mp * logf(mp);
#pragma unroll
        for (int o = 16; o; o >>= 1) u += __shfl_xor_sync(0xffffffffu, u, o);
        if (lane == 0) out[out_size - 1] = u / (float)Kc;
    }
}

// ---------------------------------------------------------------------------
extern "C" void kernel_launch(void* const* d_in, const int* in_sizes, int n_in,
                              void* d_out, int out_size) {
    const float* X    = (const float*)d_in[0];
    const float* EPS  = (const float*)d_in[1];
    const float* Wmu  = (const float*)d_in[2];
    const float* bmu  = (const float*)d_in[3];
    const float* Wsig = (const float*)d_in[4];
    const float* bsig = (const float*)d_in[5];
    const float* muc  = (const float*)d_in[6];
    const float* lsc  = (const float*)d_in[7];
    float* out = (float*)d_out;

    cudaFuncSetAttribute(fused_kernel,
                         cudaFuncAttributeMaxDynamicSharedMemorySize, SMEM_BYTES);

    prep_kernel<<<1, 1024>>>(muc, lsc);
    fused_kernel<<<NBLK, THREADS, SMEM_BYTES>>>(X, EPS, Wmu, bmu, Wsig, bsig, out);
    finalize_kernel<<<1, 256>>>(out, out_size);
}

// round 4
// speedup vs baseline: 1.4001x; 1.1271x over previous
#include <cuda_runtime.h>
#include <math.h>

// Problem constants
#define Bsz 8192
#define Kc 32
#define Dd 256
#define TILE_B 32
#define NBLK 256
#define THREADS 512

// Shared memory layout (float offsets)
//  xP   [16 rp][256 d][2]                         8192
//  zs   [32 r][256]                               8192
//  mus  [32 r][256]                               8192
//  qs   [32 r][256]                               8192
//  region C (union, 16384):
//    GEMM:    WT double buffer 2 x (WTm 4096 + WTs 4096)
//    cluster: iscT float4[2048] + mciT float4[2048] (XOR-swizzled)
//  red region
#define OFF_XP   0
#define OFF_ZS   8192
#define OFF_MU   16384
#define OFF_QS   24576
#define OFF_C    32768
#define OFF_REDP 49152   // [16][32]
#define OFF_REDG 49664   // [16]
#define OFF_C2H  49680   // [32][2]
#define OFF_CLH  49744   // [32][2]
#define OFF_C2F  49808   // [32]
#define OFF_CLF  49840   // [32]
#define OFF_FLAG 49872   // int
#define SMEM_FLOATS 49876
#define SMEM_BYTES (SMEM_FLOATS * 4)

typedef unsigned long long u64;

// Cross-block scratch
__device__ float g_gaussPart[NBLK];
__device__ float g_piPart[NBLK * Kc];
__device__ unsigned int g_count;

// ---- packed f32x2 helpers ----
__device__ __forceinline__ u64 pack2(float lo, float hi) {
    u64 r; asm("mov.b64 %0,{%1,%2};" : "=l"(r) : "f"(lo), "f"(hi)); return r;
}
__device__ __forceinline__ void unpack2(u64 v, float& lo, float& hi) {
    asm("mov.b64 {%0,%1},%2;" : "=f"(lo), "=f"(hi) : "l"(v));
}
__device__ __forceinline__ void fma2(u64& d, u64 a, u64 b) {
    asm("fma.rn.f32x2 %0,%1,%2,%0;" : "+l"(d) : "l"(a), "l"(b));
}
__device__ __forceinline__ u64 mul2(u64 a, u64 b) {
    u64 d; asm("mul.rn.f32x2 %0,%1,%2;" : "=l"(d) : "l"(a), "l"(b)); return d;
}
__device__ __forceinline__ float wredsum(float v) {
#pragma unroll
    for (int o = 16; o; o >>= 1) v += __shfl_xor_sync(0xffffffffu, v, o);
    return v;
}

// ---------------------------------------------------------------------------
// Single fused kernel: GEMMs + reparam + cluster phase + folded prep/finalize
// ---------------------------------------------------------------------------
__global__ void __launch_bounds__(THREADS)
fused_kernel(const float* __restrict__ X, const float* __restrict__ EPS,
             const float* __restrict__ Wmu, const float* __restrict__ bmu,
             const float* __restrict__ Wsig, const float* __restrict__ bsig,
             const float* __restrict__ muc, const float* __restrict__ lsc,
             float* __restrict__ out, int out_size) {
    extern __shared__ float sm[];
    float* xP  = sm + OFF_XP;
    float* zs  = sm + OFF_ZS;
    float* mus = sm + OFF_MU;
    float* qs  = sm + OFF_QS;
    float4* iscT = (float4*)(sm + OFF_C);
    float4* mciT = (float4*)(sm + OFF_C + 8192);
    float* redPi = sm + OFF_REDP;
    float* redG  = sm + OFF_REDG;
    float* c2h   = sm + OFF_C2H;
    float* clh   = sm + OFF_CLH;
    float* c2f   = sm + OFF_C2F;
    float* clf   = sm + OFF_CLF;
    int*   flag  = (int*)(sm + OFF_FLAG);

    const int t = threadIdx.x;
    const int b0 = blockIdx.x * TILE_B;
    const int wi = t >> 5, lane = t & 31;
    const int rowgrp = wi >> 2;
    const int colquad = wi & 3;
    const int e0 = (colquad * 32 + lane) * 2;

    // ---- load X tile into interleaved row-pair layout xP[rp][d][2] ----
#pragma unroll
    for (int p = 0; p < 16; ++p) {
        int i = p * THREADS + t;
        int r = i >> 8, d = i & 255;
        xP[(r >> 1) * 512 + d * 2 + (r & 1)] = X[(b0 + r) * Dd + d];
    }

    // ---- W staging decomposition per pass p ----
    const float4* pfsrc[4];
    int dstOff[4];
#pragma unroll
    for (int p = 0; p < 4; ++p) {
        int g = p * THREADS + t;
        int mm = g >> 10;
        int rr = g & 1023;
        int jj = rr & 3;
        int ee = rr >> 2;
        pfsrc[p] = (const float4*)((mm ? Wsig : Wmu) + ee * Dd) + jj;
        dstOff[p] = (mm ? 4096 : 0) + jj * 4 * 256 + ee;
    }

    u64 acc[4][2][2];
#pragma unroll
    for (int rp = 0; rp < 4; ++rp)
#pragma unroll
        for (int m = 0; m < 2; ++m) { acc[rp][m][0] = 0ull; acc[rp][m][1] = 0ull; }

    // stage chunk 0 into buffer 0
    {
        float4 pf[4];
#pragma unroll
        for (int p = 0; p < 4; ++p) pf[p] = pfsrc[p][0];
#pragma unroll
        for (int p = 0; p < 4; ++p) {
            float* dst = sm + OFF_C + dstOff[p];
            dst[0] = pf[p].x; dst[256] = pf[p].y; dst[512] = pf[p].z; dst[768] = pf[p].w;
        }
    }
    __syncthreads();   // covers xP + chunk0

    // ---- Phase A: dual GEMM, double-buffered, 1 sync per chunk ----
#pragma unroll 1
    for (int ch = 0; ch < 16; ++ch) {
        float4 pfN[4];
        if (ch < 15) {
#pragma unroll
            for (int p = 0; p < 4; ++p) pfN[p] = pfsrc[p][(ch + 1) * 4];
        }
        const float* Wb = sm + OFF_C + (ch & 1) * 8192;
        const float* WTm = Wb;
        const float* WTs = Wb + 4096;
        const int dg0 = ch * 16;
#pragma unroll
        for (int dd = 0; dd < 8; ++dd) {
            int d = dd * 2;
            float2 wmA = *(const float2*)&WTm[d * 256 + e0];
            float2 wmB = *(const float2*)&WTm[(d + 1) * 256 + e0];
            float2 wsA = *(const float2*)&WTs[d * 256 + e0];
            float2 wsB = *(const float2*)&WTs[(d + 1) * 256 + e0];
            u64 m0A = pack2(wmA.x, wmA.x), m1A = pack2(wmA.y, wmA.y);
            u64 m0B = pack2(wmB.x, wmB.x), m1B = pack2(wmB.y, wmB.y);
            u64 s0A = pack2(wsA.x, wsA.x), s1A = pack2(wsA.y, wsA.y);
            u64 s0B = pack2(wsB.x, wsB.x), s1B = pack2(wsB.y, wsB.y);
#pragma unroll
            for (int rp = 0; rp < 4; ++rp) {
                ulonglong2 xv = *(const ulonglong2*)&xP[(rowgrp * 4 + rp) * 512 + (dg0 + d) * 2];
                fma2(acc[rp][0][0], xv.x, m0A); fma2(acc[rp][0][1], xv.x, m1A);
                fma2(acc[rp][1][0], xv.x, s0A); fma2(acc[rp][1][1], xv.x, s1A);
                fma2(acc[rp][0][0], xv.y, m0B); fma2(acc[rp][0][1], xv.y, m1B);
                fma2(acc[rp][1][0], xv.y, s0B); fma2(acc[rp][1][1], xv.y, s1B);
            }
        }
        if (ch < 15) {
            float* WbN = sm + OFF_C + ((ch + 1) & 1) * 8192;
#pragma unroll
            for (int p = 0; p < 4; ++p) {
                float* dst = WbN + dstOff[p];
                dst[0] = pfN[p].x; dst[256] = pfN[p].y; dst[512] = pfN[p].z; dst[768] = pfN[p].w;
            }
            __syncthreads();
        }
    }

    // ---- Phase B: bias, reparameterize, write z, stash row vectors ----
    {
        float2 bm = *(const float2*)&bmu[e0];
        float2 bs = *(const float2*)&bsig[e0];
#pragma unroll
        for (int rp = 0; rp < 4; ++rp) {
            float mu0l, mu0h, mu1l, mu1h, ls0l, ls0h, ls1l, ls1h;
            unpack2(acc[rp][0][0], mu0l, mu0h);
            unpack2(acc[rp][0][1], mu1l, mu1h);
            unpack2(acc[rp][1][0], ls0l, ls0h);
            unpack2(acc[rp][1][1], ls1l, ls1h);
#pragma unroll
            for (int s = 0; s < 2; ++s) {
                int r = rowgrp * 8 + rp * 2 + s;
                float mu0 = (s ? mu0h : mu0l) + bm.x;
                float mu1 = (s ? mu1h : mu1l) + bm.y;
                float ls0 = (s ? ls0h : ls0l) + bs.x;
                float ls1 = (s ? ls1h : ls1l) + bs.y;
                float ez0 = __expf(ls0), ez1 = __expf(ls1);
                float2 ep = *(const float2*)&EPS[(b0 + r) * Dd + e0];
                float z0 = fmaf(sqrtf(ez0), ep.x, mu0);
                float z1 = fmaf(sqrtf(ez1), ep.y, mu1);
                float2 zv = {z0, z1};
                *(float2*)&out[(b0 + r) * Dd + e0] = zv;
                *(float2*)&zs[r * Dd + e0] = zv;
                float2 mv = {mu0, mu1};
                *(float2*)&mus[r * Dd + e0] = mv;
                float2 qv = {fmaf(mu0, mu0, ez0), fmaf(mu1, mu1, ez1)};
                *(float2*)&qs[r * Dd + e0] = qv;
            }
        }
    }
    __syncthreads();   // all GEMM smem reads done; region C reusable

    // ---- build cluster tables (XOR-swizzled) + c2/clsc, folded prep ----
    {
        const float4* lsc4 = (const float4*)lsc;
        const float4* muc4 = (const float4*)muc;
#pragma unroll
        for (int p = 0; p < 4; ++p) {
            int j = p * THREADS + t;          // [k][d4] linear, coalesced
            int k = j >> 6, d4 = j & 63;
            float4 l4 = lsc4[j];
            float4 m4 = muc4[j];
            float4 i4 = {__expf(-l4.x), __expf(-l4.y), __expf(-l4.z), __expf(-l4.w)};
            float4 mc = {m4.x * i4.x, m4.y * i4.y, m4.z * i4.z, m4.w * i4.w};
            int u = d4 * 32 + (k ^ (d4 & 31));
            iscT[u] = i4;
            mciT[u] = mc;
            float cp = m4.x * m4.x * i4.x + m4.y * m4.y * i4.y
                     + m4.z * m4.z * i4.z + m4.w * m4.w * i4.w;
            float cl = l4.x + l4.y + l4.z + l4.w;
            cp = wredsum(cp);
            cl = wredsum(cl);
            if (lane == 0) {
                int kk = p * 8 + (wi >> 1);   // == k for this (p, warp)
                int half = wi & 1;
                c2h[kk * 2 + half] = cp;
                clh[kk * 2 + half] = cl;
            }
        }
    }
    __syncthreads();
    if (t < 32) {
        c2f[t] = c2h[t * 2] + c2h[t * 2 + 1];
        clf[t] = clh[t * 2] + clh[t * 2 + 1];
    }
    __syncthreads();

    // ---- Phase C: one warp per 2 rows, lane == cluster k ----
    float c2v = c2f[lane], clv = clf[lane];
    float piAcc = 0.f, gAcc = 0.f;
    {
        const int r0 = wi * 2;
        u64 A1[2] = {0ull, 0ull}, A2[2] = {0ull, 0ull};
        u64 A3[2] = {0ull, 0ull}, A4[2] = {0ull, 0ull};
#pragma unroll 4
        for (int d4 = 0; d4 < 64; ++d4) {
            int u = d4 * 32 + (lane ^ (d4 & 31));
            float4 iv = iscT[u];
            float4 mv = mciT[u];
            u64 ivA = pack2(iv.x, iv.y), ivB = pack2(iv.z, iv.w);
            u64 mvA = pack2(mv.x, mv.y), mvB = pack2(mv.z, mv.w);
#pragma unroll
            for (int rr = 0; rr < 2; ++rr) {
                ulonglong2 zv = *(const ulonglong2*)&zs[(r0 + rr) * Dd + d4 * 4];
                ulonglong2 mw = *(const ulonglong2*)&mus[(r0 + rr) * Dd + d4 * 4];
                ulonglong2 qv = *(const ulonglong2*)&qs[(r0 + rr) * Dd + d4 * 4];
                fma2(A1[rr], mul2(zv.x, zv.x), ivA); fma2(A1[rr], mul2(zv.y, zv.y), ivB);
                fma2(A2[rr], zv.x, mvA);             fma2(A2[rr], zv.y, mvB);
                fma2(A3[rr], qv.x, ivA);             fma2(A3[rr], qv.y, ivB);
                fma2(A4[rr], mw.x, mvA);             fma2(A4[rr], mw.y, mvB);
            }
        }
#pragma unroll
        for (int rr = 0; rr < 2; ++rr) {
            float x0, x1;
            unpack2(A1[rr], x0, x1); float a1 = x0 + x1;
            unpack2(A2[rr], x0, x1); float a2 = x0 + x1;
            unpack2(A3[rr], x0, x1); float a3 = x0 + x1;
            unpack2(A4[rr], x0, x1); float a4 = x0 + x1;

            float logit = -(a1 - 2.f * a2 + c2v);
            float S = clv + a3 - 2.f * a4 + c2v;

            float mx = logit;
#pragma unroll
            for (int o = 16; o; o >>= 1) mx = fmaxf(mx, __shfl_xor_sync(0xffffffffu, mx, o));
            float p = __expf(logit - mx);
            float ssum = wredsum(p);
            float pi = p / ssum + 1e-10f;

            piAcc += pi;
            gAcc += wredsum(pi * S);
        }
    }

    // ---- block partials ----
    redPi[wi * 32 + lane] = piAcc;
    if (lane == 0) redG[wi] = gAcc;
    __syncthreads();
    if (wi == 0) {
        float ps = 0.f;
#pragma unroll
        for (int i = 0; i < 16; ++i) ps += redPi[i * 32 + lane];
        g_piPart[blockIdx.x * 32 + lane] = ps;
        if (lane == 0) {
            float gsum = 0.f;
#pragma unroll
            for (int i = 0; i < 16; ++i) gsum += redG[i];
            g_gaussPart[blockIdx.x] = gsum;
        }
    }
    __syncthreads();

    // ---- last-block folded finalize ----
    if (t == 0) {
        __threadfence();
        unsigned int old = atomicAdd(&g_count, 1u);
        *flag = (old == NBLK - 1) ? 1 : 0;
    }
    __syncthreads();
    if (*flag) {
        if (t == 0) atomicExch(&g_count, 0u);   // reset for graph replay
        __threadfence();
        // gaussian: 256 partials
        if (t < 256) {
            float g = g_gaussPart[t];
            g = wredsum(g);
            if (lane == 0) redG[wi] = g;
        }
        // pi: warp w sums blocks [w*16, w*16+16), lane == k
        {
            float ps = 0.f;
#pragma unroll
            for (int j = 0; j < 16; ++j)
                ps += g_piPart[(wi * 16 + j) * 32 + lane];
            redPi[wi * 32 + lane] = ps;
        }
        __syncthreads();
        if (t == 0) {
            float G = 0.f;
#pragma unroll
            for (int i = 0; i < 8; ++i) G += redG[i];
            out[out_size - 2] = 0.5f * G;
        }
        if (wi == 0) {
            float P = 0.f;
#pragma unroll
            for (int i = 0; i < 16; ++i) P += redPi[i * 32 + lane];
            float mp = P / (float)Bsz;
            float u = mp * logf(mp);
            u = wredsum(u);
            if (lane == 0) out[out_size - 1] = u / (float)Kc;
        }
    }
}

// ---------------------------------------------------------------------------
extern "C" void kernel_launch(void* const* d_in, const int* in_sizes, int n_in,
                              void* d_out, int out_size) {
    const float* X    = (const float*)d_in[0];
    const float* EPS  = (const float*)d_in[1];
    const float* Wmu  = (const float*)d_in[2];
    const float* bmu  = (const float*)d_in[3];
    const float* Wsig = (const float*)d_in[4];
    const float* bsig = (const float*)d_in[5];
    const float* muc  = (const float*)d_in[6];
    const float* lsc  = (const float*)d_in[7];
    float* out = (float*)d_out;

    static bool attr_set = false;
    if (!attr_set) {
        cudaFuncSetAttribute(fused_kernel,
                             cudaFuncAttributeMaxDynamicSharedMemorySize, SMEM_BYTES);
        attr_set = true;
    }
    fused_kernel<<<NBLK, THREADS, SMEM_BYTES>>>(X, EPS, Wmu, bmu, Wsig, bsig,
                                                muc, lsc, out, out_size);
}

// round 5
// speedup vs baseline: 1.6362x; 1.1687x over previous
#include <cuda_runtime.h>
#include <math.h>

// Problem constants
#define Bsz 8192
#define Kc 32
#define Dd 256
#define TILE_B 32
#define NBLK 256
#define THREADS 512
#define CH_D 32            // d per chunk
#define NCH 8              // chunks
#define WP 258             // WT row pitch (floats): bank = 8*jj + ee, conflict-free

// Shared memory layout (float offsets)
// During GEMM:
//   xP  [0, 8192)            : X tile, interleaved row-pairs
//   W   [8192, 41216)        : 2 buffers x (WTm [32][258] + WTs [32][258]) = 2*16512
// After GEMM (overlaid):
//   zs  [0, 8192)  mus [8192,16384)  qs [16384,24576)
//   iscT [24576, 32768)  mciT [32768, 40960)        (float4 tables, XOR-swizzled)
// Always live:
//   red region at 41216+
#define OFF_XP   0
#define OFF_W    8192
#define W_BUFSTR 16512      // per-buffer floats (2 mats * 32 * 258)
#define W_MATOFS 8256       // sig offset within buffer (32*258)
#define OFF_ZS   0
#define OFF_MU   8192
#define OFF_QS   16384
#define OFF_TISC 24576
#define OFF_TMCI 32768
#define OFF_REDP 41216      // [16][32]
#define OFF_REDG 41728      // [16]
#define OFF_C2H  41744      // [32][2]
#define OFF_CLH  41808      // [32][2]
#define OFF_C2F  41872      // [32]
#define OFF_CLF  41904      // [32]
#define OFF_FLAG 41936
#define SMEM_FLOATS 41940
#define SMEM_BYTES (SMEM_FLOATS * 4)

typedef unsigned long long u64;

// Cross-block scratch
__device__ float g_gaussPart[NBLK];
__device__ float g_piPart[NBLK * Kc];
__device__ unsigned int g_count;

// ---- packed f32x2 helpers ----
__device__ __forceinline__ u64 pack2(float lo, float hi) {
    u64 r; asm("mov.b64 %0,{%1,%2};" : "=l"(r) : "f"(lo), "f"(hi)); return r;
}
__device__ __forceinline__ void unpack2(u64 v, float& lo, float& hi) {
    asm("mov.b64 {%0,%1},%2;" : "=f"(lo), "=f"(hi) : "l"(v));
}
__device__ __forceinline__ void fma2(u64& d, u64 a, u64 b) {
    asm("fma.rn.f32x2 %0,%1,%2,%0;" : "+l"(d) : "l"(a), "l"(b));
}
__device__ __forceinline__ u64 mul2(u64 a, u64 b) {
    u64 d; asm("mul.rn.f32x2 %0,%1,%2;" : "=l"(d) : "l"(a), "l"(b)); return d;
}
__device__ __forceinline__ float wredsum(float v) {
#pragma unroll
    for (int o = 16; o; o >>= 1) v += __shfl_xor_sync(0xffffffffu, v, o);
    return v;
}

// ---------------------------------------------------------------------------
__global__ void __launch_bounds__(THREADS)
fused_kernel(const float* __restrict__ X, const float* __restrict__ EPS,
             const float* __restrict__ Wmu, const float* __restrict__ bmu,
             const float* __restrict__ Wsig, const float* __restrict__ bsig,
             const float* __restrict__ muc, const float* __restrict__ lsc,
             float* __restrict__ out, int out_size) {
    extern __shared__ float sm[];
    float* xP  = sm + OFF_XP;
    float* redPi = sm + OFF_REDP;
    float* redG  = sm + OFF_REDG;
    float* c2h   = sm + OFF_C2H;
    float* clh   = sm + OFF_CLH;
    float* c2f   = sm + OFF_C2F;
    float* clf   = sm + OFF_CLF;
    int*   flag  = (int*)(sm + OFF_FLAG);

    const int t = threadIdx.x;
    const int b0 = blockIdx.x * TILE_B;
    const int wi = t >> 5, lane = t & 31;
    const int rowgrp = wi >> 2;
    const int colquad = wi & 3;
    const int e0 = (colquad * 32 + lane) * 2;

    // ---- load X tile into interleaved row-pair layout xP[rp][d][2] ----
#pragma unroll
    for (int p = 0; p < 16; ++p) {
        int i = p * THREADS + t;
        int r = i >> 8, d = i & 255;
        xP[(r >> 1) * 512 + d * 2 + (r & 1)] = X[(b0 + r) * Dd + d];
    }

    // ---- staging decomposition: pass p -> mm = p>>2, half = (p>>1)&1,
    //      ee = (p&1)*128 + (t>>2), jj = t&3 ----
    const int eth = t >> 2, jth = t & 3;
    const float4* pfsrc[8];
    int dstOff[8];
#pragma unroll
    for (int p = 0; p < 8; ++p) {
        int mm = p >> 2;
        int half = (p >> 1) & 1;
        int ee = ((p & 1) << 7) + eth;
        pfsrc[p] = (const float4*)(mm ? Wsig : Wmu) + ee * 64 + half * 4 + jth;
        dstOff[p] = mm * W_MATOFS + (half * 16 + jth * 4) * WP + ee;
    }

    u64 acc[4][2][2];
#pragma unroll
    for (int rp = 0; rp < 4; ++rp)
#pragma unroll
        for (int m = 0; m < 2; ++m) { acc[rp][m][0] = 0ull; acc[rp][m][1] = 0ull; }

    // stage chunk 0 into buffer 0
    {
        float4 pf[8];
#pragma unroll
        for (int p = 0; p < 8; ++p) pf[p] = pfsrc[p][0];
#pragma unroll
        for (int p = 0; p < 8; ++p) {
            float* dst = sm + OFF_W + dstOff[p];
            dst[0] = pf[p].x; dst[WP] = pf[p].y; dst[2*WP] = pf[p].z; dst[3*WP] = pf[p].w;
        }
    }
    __syncthreads();   // covers xP + chunk0

    // ---- Phase A: dual GEMM, 8 chunks of 32 d, double-buffered ----
#pragma unroll 1
    for (int ch = 0; ch < NCH; ++ch) {
        float4 pf[8];
        if (ch < NCH - 1) {
#pragma unroll
            for (int p = 0; p < 8; ++p) pf[p] = pfsrc[p][(ch + 1) * 8];
        }
        const float* Wb  = sm + OFF_W + (ch & 1) * W_BUFSTR;
        const float* WTm = Wb;
        const float* WTs = Wb + W_MATOFS;
        const int dg0 = ch * CH_D;
#pragma unroll
        for (int dd = 0; dd < 16; ++dd) {
            int d = dd * 2;
            float2 wmA = *(const float2*)&WTm[d * WP + e0];
            float2 wmB = *(const float2*)&WTm[(d + 1) * WP + e0];
            float2 wsA = *(const float2*)&WTs[d * WP + e0];
            float2 wsB = *(const float2*)&WTs[(d + 1) * WP + e0];
            u64 m0A = pack2(wmA.x, wmA.x), m1A = pack2(wmA.y, wmA.y);
            u64 m0B = pack2(wmB.x, wmB.x), m1B = pack2(wmB.y, wmB.y);
            u64 s0A = pack2(wsA.x, wsA.x), s1A = pack2(wsA.y, wsA.y);
            u64 s0B = pack2(wsB.x, wsB.x), s1B = pack2(wsB.y, wsB.y);
#pragma unroll
            for (int rp = 0; rp < 4; ++rp) {
                ulonglong2 xv = *(const ulonglong2*)&xP[(rowgrp * 4 + rp) * 512 + (dg0 + d) * 2];
                fma2(acc[rp][0][0], xv.x, m0A); fma2(acc[rp][0][1], xv.x, m1A);
                fma2(acc[rp][1][0], xv.x, s0A); fma2(acc[rp][1][1], xv.x, s1A);
                fma2(acc[rp][0][0], xv.y, m0B); fma2(acc[rp][0][1], xv.y, m1B);
                fma2(acc[rp][1][0], xv.y, s0B); fma2(acc[rp][1][1], xv.y, s1B);
            }
        }
        if (ch < NCH - 1) {
            float* WbN = sm + OFF_W + ((ch + 1) & 1) * W_BUFSTR;
#pragma unroll
            for (int p = 0; p < 8; ++p) {
                float* dst = WbN + dstOff[p];
                dst[0] = pf[p].x; dst[WP] = pf[p].y; dst[2*WP] = pf[p].z; dst[3*WP] = pf[p].w;
            }
            __syncthreads();
        }
    }
    __syncthreads();   // all reads of xP/W done; overlays become safe

    float* zs  = sm + OFF_ZS;
    float* mus = sm + OFF_MU;
    float* qs  = sm + OFF_QS;
    float4* iscT = (float4*)(sm + OFF_TISC);
    float4* mciT = (float4*)(sm + OFF_TMCI);

    // ---- Phase B: bias, reparameterize, write z, stash row vectors ----
    {
        float2 bm = *(const float2*)&bmu[e0];
        float2 bs = *(const float2*)&bsig[e0];
#pragma unroll
        for (int rp = 0; rp < 4; ++rp) {
            float mu0l, mu0h, mu1l, mu1h, ls0l, ls0h, ls1l, ls1h;
            unpack2(acc[rp][0][0], mu0l, mu0h);
            unpack2(acc[rp][0][1], mu1l, mu1h);
            unpack2(acc[rp][1][0], ls0l, ls0h);
            unpack2(acc[rp][1][1], ls1l, ls1h);
#pragma unroll
            for (int s = 0; s < 2; ++s) {
                int r = rowgrp * 8 + rp * 2 + s;
                float mu0 = (s ? mu0h : mu0l) + bm.x;
                float mu1 = (s ? mu1h : mu1l) + bm.y;
                float ls0 = (s ? ls0h : ls0l) + bs.x;
                float ls1 = (s ? ls1h : ls1l) + bs.y;
                float ez0 = __expf(ls0), ez1 = __expf(ls1);
                float2 ep = *(const float2*)&EPS[(b0 + r) * Dd + e0];
                float z0 = fmaf(sqrtf(ez0), ep.x, mu0);
                float z1 = fmaf(sqrtf(ez1), ep.y, mu1);
                float2 zv = {z0, z1};
                *(float2*)&out[(b0 + r) * Dd + e0] = zv;
                *(float2*)&zs[r * Dd + e0] = zv;
                float2 mv = {mu0, mu1};
                *(float2*)&mus[r * Dd + e0] = mv;
                float2 qv = {fmaf(mu0, mu0, ez0), fmaf(mu1, mu1, ez1)};
                *(float2*)&qs[r * Dd + e0] = qv;
            }
        }
    }

    // ---- build cluster tables (XOR-swizzled) + c2/clsc ----
    {
        const float4* lsc4 = (const float4*)lsc;
        const float4* muc4 = (const float4*)muc;
#pragma unroll
        for (int p = 0; p < 4; ++p) {
            int j = p * THREADS + t;          // [k][d4] linear, coalesced
            int k = j >> 6, d4 = j & 63;
            float4 l4 = lsc4[j];
            float4 m4 = muc4[j];
            float4 i4 = {__expf(-l4.x), __expf(-l4.y), __expf(-l4.z), __expf(-l4.w)};
            float4 mc = {m4.x * i4.x, m4.y * i4.y, m4.z * i4.z, m4.w * i4.w};
            int u = d4 * 32 + (k ^ (d4 & 31));
            iscT[u] = i4;
            mciT[u] = mc;
            float cp = m4.x * m4.x * i4.x + m4.y * m4.y * i4.y
                     + m4.z * m4.z * i4.z + m4.w * m4.w * i4.w;
            float cl = l4.x + l4.y + l4.z + l4.w;
            cp = wredsum(cp);
            cl = wredsum(cl);
            if (lane == 0) {
                int kk = p * 8 + (wi >> 1);
                int half = wi & 1;
                c2h[kk * 2 + half] = cp;
                clh[kk * 2 + half] = cl;
            }
        }
    }
    __syncthreads();
    if (t < 32) {
        c2f[t] = c2h[t * 2] + c2h[t * 2 + 1];
        clf[t] = clh[t * 2] + clh[t * 2 + 1];
    }
    __syncthreads();

    // ---- Phase C: one warp per 2 rows, lane == cluster k ----
    float c2v = c2f[lane], clv = clf[lane];
    float piAcc = 0.f, gAcc = 0.f;
    {
        const int r0 = wi * 2;
        u64 A1[2] = {0ull, 0ull}, A2[2] = {0ull, 0ull};
        u64 A3[2] = {0ull, 0ull}, A4[2] = {0ull, 0ull};
#pragma unroll 4
        for (int d4 = 0; d4 < 64; ++d4) {
            int u = d4 * 32 + (lane ^ (d4 & 31));
            float4 iv = iscT[u];
            float4 mv = mciT[u];
            u64 ivA = pack2(iv.x, iv.y), ivB = pack2(iv.z, iv.w);
            u64 mvA = pack2(mv.x, mv.y), mvB = pack2(mv.z, mv.w);
#pragma unroll
            for (int rr = 0; rr < 2; ++rr) {
                ulonglong2 zv = *(const ulonglong2*)&zs[(r0 + rr) * Dd + d4 * 4];
                ulonglong2 mw = *(const ulonglong2*)&mus[(r0 + rr) * Dd + d4 * 4];
                ulonglong2 qv = *(const ulonglong2*)&qs[(r0 + rr) * Dd + d4 * 4];
                fma2(A1[rr], mul2(zv.x, zv.x), ivA); fma2(A1[rr], mul2(zv.y, zv.y), ivB);
                fma2(A2[rr], zv.x, mvA);             fma2(A2[rr], zv.y, mvB);
                fma2(A3[rr], qv.x, ivA);             fma2(A3[rr], qv.y, ivB);
                fma2(A4[rr], mw.x, mvA);             fma2(A4[rr], mw.y, mvB);
            }
        }
#pragma unroll
        for (int rr = 0; rr < 2; ++rr) {
            float x0, x1;
            unpack2(A1[rr], x0, x1); float a1 = x0 + x1;
            unpack2(A2[rr], x0, x1); float a2 = x0 + x1;
            unpack2(A3[rr], x0, x1); float a3 = x0 + x1;
            unpack2(A4[rr], x0, x1); float a4 = x0 + x1;

            float logit = -(a1 - 2.f * a2 + c2v);
            float S = clv + a3 - 2.f * a4 + c2v;

            float mx = logit;
#pragma unroll
            for (int o = 16; o; o >>= 1) mx = fmaxf(mx, __shfl_xor_sync(0xffffffffu, mx, o));
            float p = __expf(logit - mx);
            float ssum = wredsum(p);
            float pi = p / ssum + 1e-10f;

            piAcc += pi;
            gAcc += wredsum(pi * S);
        }
    }

    // ---- block partials ----
    redPi[wi * 32 + lane] = piAcc;
    if (lane == 0) redG[wi] = gAcc;
    __syncthreads();
    if (wi == 0) {
        float ps = 0.f;
#pragma unroll
        for (int i = 0; i < 16; ++i) ps += redPi[i * 32 + lane];
        g_piPart[blockIdx.x * 32 + lane] = ps;
        if (lane == 0) {
            float gsum = 0.f;
#pragma unroll
            for (int i = 0; i < 16; ++i) gsum += redG[i];
            g_gaussPart[blockIdx.x] = gsum;
        }
    }
    __syncthreads();

    // ---- last-block folded finalize ----
    if (t == 0) {
        __threadfence();
        unsigned int old = atomicAdd(&g_count, 1u);
        *flag = (old == NBLK - 1) ? 1 : 0;
    }
    __syncthreads();
    if (*flag) {
        if (t == 0) atomicExch(&g_count, 0u);   // reset for graph replay
        __threadfence();
        if (t < 256) {
            float g = g_gaussPart[t];
            g = wredsum(g);
            if (lane == 0) redG[wi] = g;
        }
        {
            float ps = 0.f;
#pragma unroll
            for (int j = 0; j < 16; ++j)
                ps += g_piPart[(wi * 16 + j) * 32 + lane];
            redPi[wi * 32 + lane] = ps;
        }
        __syncthreads();
        if (t == 0) {
            float G = 0.f;
#pragma unroll
            for (int i = 0; i < 8; ++i) G += redG[i];
            out[out_size - 2] = 0.5f * G;
        }
        if (wi == 0) {
            float P = 0.f;
#pragma unroll
            for (int i = 0; i < 16; ++i) P += redPi[i * 32 + lane];
            float mp = P / (float)Bsz;
            float u = mp * logf(mp);
            u = wredsum(u);
            if (lane == 0) out[out_size - 1] = u / (float)Kc;
        }
    }
}

// ---------------------------------------------------------------------------
extern "C" void kernel_launch(void* const* d_in, const int* in_sizes, int n_in,
                              void* d_out, int out_size) {
    const float* X    = (const float*)d_in[0];
    const float* EPS  = (const float*)d_in[1];
    const float* Wmu  = (const float*)d_in[2];
    const float* bmu  = (const float*)d_in[3];
    const float* Wsig = (const float*)d_in[4];
    const float* bsig = (const float*)d_in[5];
    const float* muc  = (const float*)d_in[6];
    const float* lsc  = (const float*)d_in[7];
    float* out = (float*)d_out;

    static bool attr_set = false;
    if (!attr_set) {
        cudaFuncSetAttribute(fused_kernel,
                             cudaFuncAttributeMaxDynamicSharedMemorySize, SMEM_BYTES);
        attr_set = true;
    }
    fused_kernel<<<NBLK, THREADS, SMEM_BYTES>>>(X, EPS, Wmu, bmu, Wsig, bsig,
                                                muc, lsc, out, out_size);
}

// round 6
// speedup vs baseline: 2.2708x; 1.3878x over previous
#include <cuda_runtime.h>
#include <math.h>
#include <stdint.h>

// Problem constants
#define Bsz 8192
#define Kc 32
#define Dd 256
#define TILE_B 32
#define NBLK 256
#define THREADS 512
#define PZ 264              // row pitch for z/mu/q planes (floats)

// Shared memory layout (float offsets)
// GEMM phase:
//   aFrag [0, 8192)       : A fragments [kt 32][mt 2][lane 32][4]
//   bFrag [8192, 40960)   : 2 buffers x 16384 ([ktc 4][nt 64][reg 2][lane 32])
// Overlay after GEMM:
//   zs [0,8448) mus [8448,16896) qs [16896,25344)   (pitch 264)
//   iscT [25344,33536) mciT [33536,41728)           (float4 tables)
// Always live: reduction region at 41728+
#define OFF_AF   0
#define OFF_BF   8192
#define BUFSTR   16384
#define OFF_ZS   0
#define OFF_MU   8448
#define OFF_QS   16896
#define OFF_TISC 25344
#define OFF_TMCI 33536
#define OFF_REDP 41728
#define OFF_REDG 42240
#define OFF_C2H  42256
#define OFF_CLH  42320
#define OFF_C2F  42384
#define OFF_CLF  42416
#define OFF_FLAG 42448
#define SMEM_FLOATS 42452
#define SMEM_BYTES (SMEM_FLOATS * 4)

typedef unsigned long long u64;

// Cross-block scratch
__device__ float g_gaussPart[NBLK];
__device__ float g_piPart[NBLK * Kc];
__device__ unsigned int g_count;

// ---- helpers ----
__device__ __forceinline__ uint32_t f2tf32(float f) {
    uint32_t r; asm("cvt.rna.tf32.f32 %0,%1;" : "=r"(r) : "f"(f)); return r;
}
__device__ __forceinline__ u64 pack2(float lo, float hi) {
    u64 r; asm("mov.b64 %0,{%1,%2};" : "=l"(r) : "f"(lo), "f"(hi)); return r;
}
__device__ __forceinline__ void unpack2(u64 v, float& lo, float& hi) {
    asm("mov.b64 {%0,%1},%2;" : "=f"(lo), "=f"(hi) : "l"(v));
}
__device__ __forceinline__ void fma2(u64& d, u64 a, u64 b) {
    asm("fma.rn.f32x2 %0,%1,%2,%0;" : "+l"(d) : "l"(a), "l"(b));
}
__device__ __forceinline__ u64 mul2(u64 a, u64 b) {
    u64 d; asm("mul.rn.f32x2 %0,%1,%2;" : "=l"(d) : "l"(a), "l"(b)); return d;
}
__device__ __forceinline__ float wredsum(float v) {
#pragma unroll
    for (int o = 16; o; o >>= 1) v += __shfl_xor_sync(0xffffffffu, v, o);
    return v;
}
__device__ __forceinline__ void mma_tf32(float* d, const uint32_t* a,
                                         uint32_t b0, uint32_t b1) {
    asm volatile(
        "mma.sync.aligned.m16n8k8.row.col.f32.tf32.tf32.f32 "
        "{%0,%1,%2,%3},{%4,%5,%6,%7},{%8,%9},{%0,%1,%2,%3};"
        : "+f"(d[0]), "+f"(d[1]), "+f"(d[2]), "+f"(d[3])
        : "r"(a[0]), "r"(a[1]), "r"(a[2]), "r"(a[3]), "r"(b0), "r"(b1));
}

// ---------------------------------------------------------------------------
__global__ void __launch_bounds__(THREADS)
fused_kernel(const float* __restrict__ X, const float* __restrict__ EPS,
             const float* __restrict__ Wmu, const float* __restrict__ bmu,
             const float* __restrict__ Wsig, const float* __restrict__ bsig,
             const float* __restrict__ muc, const float* __restrict__ lsc,
             float* __restrict__ out, int out_size) {
    extern __shared__ float sm[];
    uint32_t* smU = (uint32_t*)sm;
    float* redPi = sm + OFF_REDP;
    float* redG  = sm + OFF_REDG;
    float* c2h   = sm + OFF_C2H;
    float* clh   = sm + OFF_CLH;
    float* c2f   = sm + OFF_C2F;
    float* clf   = sm + OFF_CLF;
    int*   flag  = (int*)(sm + OFF_FLAG);

    const int t = threadIdx.x;
    const int b0 = blockIdx.x * TILE_B;
    const int wi = t >> 5, lane = t & 31;

    // ============ X -> A fragments (tf32) ============
#pragma unroll
    for (int p = 0; p < 16; ++p) {
        int i = p * THREADS + t;
        int r = i >> 8, d = i & 255;
        uint32_t v = f2tf32(X[(b0 + r) * Dd + d]);
        int mt = r >> 4, rl = r & 15, g = rl & 7, hi = rl >> 3;
        int kt = d >> 3, dc = d & 7, tg = dc & 3, kh = dc >> 2;
        smU[OFF_AF + ((kt * 2 + mt) * 32 + g * 4 + tg) * 4 + (hi + 2 * kh)] = v;
    }

    // ============ W staging setup ============
    // thread covers: e = p*64 + (t>>3), f4 = t&7  (p = 0..7; p<4 -> Wmu, else Wsig)
    const int t8 = t >> 3, f4 = t & 7;
    const float4* am4 = (const float4*)Wmu  + t8 * 64 + f4;   // + p*4096 + ch*8
    const float4* as4 = (const float4*)Wsig + t8 * 64 + f4;
    const int ktc_s = f4 >> 1, reg_s = f4 & 1;
    const int eg_s = t8 & 7;
    // dstBase(p) = ktc*4096 + (p*8 + (t>>6))*64 + reg*32 + (eg^f4)*4
    const int dstBase = ktc_s * 4096 + (t >> 6) * 64 + reg_s * 32 + ((eg_s ^ f4) * 4);

    float acc[8][4];
#pragma unroll
    for (int n = 0; n < 8; ++n)
#pragma unroll
        for (int q = 0; q < 4; ++q) acc[n][q] = 0.f;

    const int mt = wi >> 3;
    const int ntb = (wi & 7) * 8;

    // stage chunk 0 into buffer 0
    {
#pragma unroll
        for (int p = 0; p < 8; ++p) {
            float4 v = (p < 4) ? am4[p * 4096] : as4[(p - 4) * 4096];
            uint4 c = {f2tf32(v.x), f2tf32(v.y), f2tf32(v.z), f2tf32(v.w)};
            *(uint4*)&smU[OFF_BF + dstBase + p * 512] = c;
        }
    }
    __syncthreads();

    // ============ GEMM mainloop: 8 chunks of 32 d ============
#pragma unroll 1
    for (int ch = 0; ch < 8; ++ch) {
        float4 pf[8];
        if (ch < 7) {
#pragma unroll
            for (int p = 0; p < 8; ++p)
                pf[p] = (p < 4) ? am4[p * 4096 + (ch + 1) * 8]
                                : as4[(p - 4) * 4096 + (ch + 1) * 8];
        }
        const uint32_t* bufB = smU + OFF_BF + (ch & 1) * BUFSTR;
#pragma unroll
        for (int ktc = 0; ktc < 4; ++ktc) {
            uint32_t a[4];
            *(uint4*)a = *(const uint4*)&smU[OFF_AF + (((ch * 4 + ktc) * 2 + mt) * 32 + lane) * 4];
            const int p0 = lane ^ (ktc * 8);
            const int p1 = lane ^ (ktc * 8 + 4);
            const uint32_t* base = bufB + ktc * 4096 + ntb * 64;
#pragma unroll
            for (int nt = 0; nt < 8; ++nt) {
                uint32_t b0r = base[nt * 64 + p0];
                uint32_t b1r = base[nt * 64 + 32 + p1];
                mma_tf32(acc[nt], a, b0r, b1r);
            }
        }
        if (ch < 7) {
            uint32_t* dstB = smU + OFF_BF + ((ch + 1) & 1) * BUFSTR + dstBase;
#pragma unroll
            for (int p = 0; p < 8; ++p) {
                uint4 c = {f2tf32(pf[p].x), f2tf32(pf[p].y), f2tf32(pf[p].z), f2tf32(pf[p].w)};
                *(uint4*)&dstB[p * 512] = c;
            }
            __syncthreads();
        }
    }
    __syncthreads();   // all fragment reads done; overlays safe

    // ============ scatter C fragments to mu / ls planes ============
    {
        float* plane = ((wi & 7) < 4) ? (sm + OFF_MU) : (sm + OFF_QS);
        int cb0 = ((wi & 7) & 3) * 64;
        int g = lane >> 2, tg = lane & 3;
        int r0 = mt * 16 + g;
#pragma unroll
        for (int nt = 0; nt < 8; ++nt) {
            int c = cb0 + nt * 8 + 2 * tg;
            float2 lo = {acc[nt][0], acc[nt][1]};
            float2 hi = {acc[nt][2], acc[nt][3]};
            *(float2*)&plane[r0 * PZ + c] = lo;
            *(float2*)&plane[(r0 + 8) * PZ + c] = hi;
        }
    }
    __syncthreads();

    float* zs  = sm + OFF_ZS;
    float* mus = sm + OFF_MU;
    float* qs  = sm + OFF_QS;
    float4* iscT = (float4*)(sm + OFF_TISC);
    float4* mciT = (float4*)(sm + OFF_TMCI);

    // ============ Phase B: bias + reparameterize ============
#pragma unroll
    for (int p = 0; p < 16; ++p) {
        int i = p * THREADS + t;
        int r = i >> 8, e = i & 255;
        float mu = mus[r * PZ + e] + __ldg(&bmu[e]);
        float ls = qs[r * PZ + e] + __ldg(&bsig[e]);
        float ez = __expf(ls);
        float ep = EPS[(b0 + r) * Dd + e];
        float z = fmaf(sqrtf(ez), ep, mu);
        out[(b0 + r) * Dd + e] = z;
        zs[r * PZ + e]  = z;
        mus[r * PZ + e] = mu;
        qs[r * PZ + e]  = fmaf(mu, mu, ez);
    }

    // ============ build cluster tables (XOR-swizzled) + c2/clsc ============
    {
        const float4* lsc4 = (const float4*)lsc;
        const float4* muc4 = (const float4*)muc;
#pragma unroll
        for (int p = 0; p < 4; ++p) {
            int j = p * THREADS + t;
            int k = j >> 6, d4 = j & 63;
            float4 l4 = lsc4[j];
            float4 m4 = muc4[j];
            float4 i4 = {__expf(-l4.x), __expf(-l4.y), __expf(-l4.z), __expf(-l4.w)};
            float4 mc = {m4.x * i4.x, m4.y * i4.y, m4.z * i4.z, m4.w * i4.w};
            int u = d4 * 32 + (k ^ (d4 & 31));
            iscT[u] = i4;
            mciT[u] = mc;
            float cp = m4.x * m4.x * i4.x + m4.y * m4.y * i4.y
                     + m4.z * m4.z * i4.z + m4.w * m4.w * i4.w;
            float cl = l4.x + l4.y + l4.z + l4.w;
            cp = wredsum(cp);
            cl = wredsum(cl);
            if (lane == 0) {
                int kk = p * 8 + (wi >> 1);
                int half = wi & 1;
                c2h[kk * 2 + half] = cp;
                clh[kk * 2 + half] = cl;
            }
        }
    }
    __syncthreads();
    if (t < 32) {
        c2f[t] = c2h[t * 2] + c2h[t * 2 + 1];
        clf[t] = clh[t * 2] + clh[t * 2 + 1];
    }
    __syncthreads();

    // ============ Phase C: one warp per 2 rows, lane == cluster k ============
    float c2v = c2f[lane], clv = clf[lane];
    float piAcc = 0.f, gAcc = 0.f;
    {
        const int r0 = wi * 2;
        u64 A1[2] = {0ull, 0ull}, A2[2] = {0ull, 0ull};
        u64 A3[2] = {0ull, 0ull}, A4[2] = {0ull, 0ull};
#pragma unroll 4
        for (int d4 = 0; d4 < 64; ++d4) {
            int u = d4 * 32 + (lane ^ (d4 & 31));
            float4 iv = iscT[u];
            float4 mv = mciT[u];
            u64 ivA = pack2(iv.x, iv.y), ivB = pack2(iv.z, iv.w);
            u64 mvA = pack2(mv.x, mv.y), mvB = pack2(mv.z, mv.w);
#pragma unroll
            for (int rr = 0; rr < 2; ++rr) {
                ulonglong2 zv = *(const ulonglong2*)&zs[(r0 + rr) * PZ + d4 * 4];
                ulonglong2 mw = *(const ulonglong2*)&mus[(r0 + rr) * PZ + d4 * 4];
                ulonglong2 qv = *(const ulonglong2*)&qs[(r0 + rr) * PZ + d4 * 4];
                fma2(A1[rr], mul2(zv.x, zv.x), ivA); fma2(A1[rr], mul2(zv.y, zv.y), ivB);
                fma2(A2[rr], zv.x, mvA);             fma2(A2[rr], zv.y, mvB);
                fma2(A3[rr], qv.x, ivA);             fma2(A3[rr], qv.y, ivB);
                fma2(A4[rr], mw.x, mvA);             fma2(A4[rr], mw.y, mvB);
            }
        }
#pragma unroll
        for (int rr = 0; rr < 2; ++rr) {
            float x0, x1;
            unpack2(A1[rr], x0, x1); float a1 = x0 + x1;
            unpack2(A2[rr], x0, x1); float a2 = x0 + x1;
            unpack2(A3[rr], x0, x1); float a3 = x0 + x1;
            unpack2(A4[rr], x0, x1); float a4 = x0 + x1;

            float logit = -(a1 - 2.f * a2 + c2v);
            float S = clv + a3 - 2.f * a4 + c2v;

            float mx = logit;
#pragma unroll
            for (int o = 16; o; o >>= 1) mx = fmaxf(mx, __shfl_xor_sync(0xffffffffu, mx, o));
            float p = __expf(logit - mx);
            float ssum = wredsum(p);
            float pi = p / ssum + 1e-10f;

            piAcc += pi;
            gAcc += wredsum(pi * S);
        }
    }

    // ---- block partials ----
    redPi[wi * 32 + lane] = piAcc;
    if (lane == 0) redG[wi] = gAcc;
    __syncthreads();
    if (wi == 0) {
        float ps = 0.f;
#pragma unroll
        for (int i = 0; i < 16; ++i) ps += redPi[i * 32 + lane];
        g_piPart[blockIdx.x * 32 + lane] = ps;
        if (lane == 0) {
            float gsum = 0.f;
#pragma unroll
            for (int i = 0; i < 16; ++i) gsum += redG[i];
            g_gaussPart[blockIdx.x] = gsum;
        }
    }
    __syncthreads();

    // ---- last-block folded finalize ----
    if (t == 0) {
        __threadfence();
        unsigned int old = atomicAdd(&g_count, 1u);
        *flag = (old == NBLK - 1) ? 1 : 0;
    }
    __syncthreads();
    if (*flag) {
        if (t == 0) atomicExch(&g_count, 0u);
        __threadfence();
        if (t < 256) {
            float g = g_gaussPart[t];
            g = wredsum(g);
            if (lane == 0) redG[wi] = g;
        }
        {
            float ps = 0.f;
#pragma unroll
            for (int j = 0; j < 16; ++j)
                ps += g_piPart[(wi * 16 + j) * 32 + lane];
            redPi[wi * 32 + lane] = ps;
        }
        __syncthreads();
        if (t == 0) {
            float G = 0.f;
#pragma unroll
            for (int i = 0; i < 8; ++i) G += redG[i];
            out[out_size - 2] = 0.5f * G;
        }
        if (wi == 0) {
            float P = 0.f;
#pragma unroll
            for (int i = 0; i < 16; ++i) P += redPi[i * 32 + lane];
            float mp = P / (float)Bsz;
            float u = mp * logf(mp);
            u = wredsum(u);
            if (lane == 0) out[out_size - 1] = u / (float)Kc;
        }
    }
}

// ---------------------------------------------------------------------------
extern "C" void kernel_launch(void* const* d_in, const int* in_sizes, int n_in,
                              void* d_out, int out_size) {
    const float* X    = (const float*)d_in[0];
    const float* EPS  = (const float*)d_in[1];
    const float* Wmu  = (const float*)d_in[2];
    const float* bmu  = (const float*)d_in[3];
    const float* Wsig = (const float*)d_in[4];
    const float* bsig = (const float*)d_in[5];
    const float* muc  = (const float*)d_in[6];
    const float* lsc  = (const float*)d_in[7];
    float* out = (float*)d_out;

    static bool attr_set = false;
    if (!attr_set) {
        cudaFuncSetAttribute(fused_kernel,
                             cudaFuncAttributeMaxDynamicSharedMemorySize, SMEM_BYTES);
        attr_set = true;
    }
    fused_kernel<<<NBLK, THREADS, SMEM_BYTES>>>(X, EPS, Wmu, bmu, Wsig, bsig,
                                                muc, lsc, out, out_size);
}

// round 8
// speedup vs baseline: 2.9753x; 1.3103x over previous
#include <cuda_runtime.h>
#include <math.h>
#include <stdint.h>

// Problem constants
#define Bsz 8192
#define Kc 32
#define Dd 256
#define TILE_B 32
#define NBLK 256
#define THREADS 512

// Shared memory layout (float offsets)
// GEMM phase:
//   aFrag [0, 8192)       : A fragments [kt 32][mt 2][lane 32][reg 4]
//   bFrag [8192, 40960)   : 2 buffers x 16384 ([ktc 4][nt 64][reg 2][lane-swz 32])
// Overlay after GEMM (PA regions are 64x256 tf32 = 16384 words EACH):
//   PA1 [0,16384)      : phase-C GEMM1 A frags (z^2 rows 0-31, q rows 32-63)
//   PA2 [16384,32768)  : phase-C GEMM2 A frags (z rows 0-31, mu rows 32-63)
//   ISCF[32768,40960)  : isc B frags [kt 32][ntc 4][reg 2][lane-swz 32]
//   MCIF[40960,49152)  : mci B frags
//   DOTS[49152,53376)  : [4 dots][32 r][33]
// Always live: reduction region at 53376+
#define OFF_AF   0
#define OFF_BF   8192
#define BUFSTR   16384
#define OFF_PA1  0
#define OFF_PA2  16384
#define OFF_ISCF 32768
#define OFF_MCIF 40960
#define OFF_DOTS 49152
#define OFF_REDP 53376
#define OFF_REDG 53888
#define OFF_C2H  53904
#define OFF_CLH  53968
#define OFF_C2F  54032
#define OFF_CLF  54064
#define OFF_FLAG 54096
#define SMEM_FLOATS 54100
#define SMEM_BYTES (SMEM_FLOATS * 4)

// Cross-block scratch
__device__ float g_gaussPart[NBLK];
__device__ float g_piPart[NBLK * Kc];
__device__ unsigned int g_count;

// ---- helpers ----
__device__ __forceinline__ uint32_t f2tf32(float f) {
    uint32_t r; asm("cvt.rna.tf32.f32 %0,%1;" : "=r"(r) : "f"(f)); return r;
}
__device__ __forceinline__ float wredsum(float v) {
#pragma unroll
    for (int o = 16; o; o >>= 1) v += __shfl_xor_sync(0xffffffffu, v, o);
    return v;
}
__device__ __forceinline__ void mma_tf32(float* d, const uint32_t* a,
                                         uint32_t b0, uint32_t b1) {
    asm volatile(
        "mma.sync.aligned.m16n8k8.row.col.f32.tf32.tf32.f32 "
        "{%0,%1,%2,%3},{%4,%5,%6,%7},{%8,%9},{%0,%1,%2,%3};"
        : "+f"(d[0]), "+f"(d[1]), "+f"(d[2]), "+f"(d[3])
        : "r"(a[0]), "r"(a[1]), "r"(a[2]), "r"(a[3]), "r"(b0), "r"(b1));
}

// ---------------------------------------------------------------------------
__global__ void __launch_bounds__(THREADS)
fused_kernel(const float* __restrict__ X, const float* __restrict__ EPS,
             const float* __restrict__ Wmu, const float* __restrict__ bmu,
             const float* __restrict__ Wsig, const float* __restrict__ bsig,
             const float* __restrict__ muc, const float* __restrict__ lsc,
             float* __restrict__ out, int out_size) {
    extern __shared__ float sm[];
    uint32_t* smU = (uint32_t*)sm;
    float* dots  = sm + OFF_DOTS;
    float* redPi = sm + OFF_REDP;
    float* redG  = sm + OFF_REDG;
    float* c2h   = sm + OFF_C2H;
    float* clh   = sm + OFF_CLH;
    float* c2f   = sm + OFF_C2F;
    float* clf   = sm + OFF_CLF;
    int*   flag  = (int*)(sm + OFF_FLAG);

    const int t = threadIdx.x;
    const int b0 = blockIdx.x * TILE_B;
    const int wi = t >> 5, lane = t & 31;
    const int g = lane >> 2, tg = lane & 3;
    const int cb = wi * 16;              // this warp's col block (0..240)

    // ============ X -> A fragments (tf32) ============
#pragma unroll
    for (int p = 0; p < 16; ++p) {
        int i = p * THREADS + t;
        int r = i >> 8, d = i & 255;
        uint32_t v = f2tf32(X[(b0 + r) * Dd + d]);
        int mt = r >> 4, rl = r & 15, gg = rl & 7, hi = rl >> 3;
        int kt = d >> 3, dc = d & 7, tgx = dc & 3, kh = dc >> 2;
        smU[OFF_AF + (((kt * 2 + mt) * 32) + gg * 4 + tgx) * 4 + (hi + 2 * kh)] = v;
    }

    // ============ W staging ============
    const int t8 = t >> 3, f4 = t & 7;
    const float4* am4 = (const float4*)Wmu  + t8 * 64 + f4;
    const float4* as4 = (const float4*)Wsig + t8 * 64 + f4;
    const int ktc_s = f4 >> 1, reg_s = f4 & 1;
    const int eg_s = t8 & 7;
    const int dstBase = ktc_s * 4096 + (t >> 6) * 64 + reg_s * 32 + ((eg_s ^ f4) * 4);

    float acc[2][2][2][4];   // [mt][mat][j][creg]
#pragma unroll
    for (int a = 0; a < 2; ++a)
#pragma unroll
        for (int b = 0; b < 2; ++b)
#pragma unroll
            for (int c = 0; c < 2; ++c)
#pragma unroll
                for (int q = 0; q < 4; ++q) acc[a][b][c][q] = 0.f;

    // stage chunk 0
    {
#pragma unroll
        for (int p = 0; p < 8; ++p) {
            float4 v = (p < 4) ? am4[p * 4096] : as4[(p - 4) * 4096];
            uint4 c = {f2tf32(v.x), f2tf32(v.y), f2tf32(v.z), f2tf32(v.w)};
            *(uint4*)&smU[OFF_BF + dstBase + p * 512] = c;
        }
    }
    __syncthreads();

    // ============ main GEMM: 8 chunks of 32 d ============
#pragma unroll 1
    for (int ch = 0; ch < 8; ++ch) {
        float4 pf[8];
        if (ch < 7) {
#pragma unroll
            for (int p = 0; p < 8; ++p)
                pf[p] = (p < 4) ? am4[p * 4096 + (ch + 1) * 8]
                                : as4[(p - 4) * 4096 + (ch + 1) * 8];
        }
        const uint32_t* bufB = smU + OFF_BF + (ch & 1) * BUFSTR;
#pragma unroll
        for (int ktc = 0; ktc < 4; ++ktc) {
            int kt = ch * 4 + ktc;
            uint32_t a0[4], a1[4];
            *(uint4*)a0 = *(const uint4*)&smU[OFF_AF + ((kt * 2 + 0) * 32 + lane) * 4];
            *(uint4*)a1 = *(const uint4*)&smU[OFF_AF + ((kt * 2 + 1) * 32 + lane) * 4];
            const int p0 = lane ^ (ktc * 8);
            const int p1 = lane ^ (ktc * 8 + 4);
#pragma unroll
            for (int m = 0; m < 2; ++m) {
#pragma unroll
                for (int j = 0; j < 2; ++j) {
                    int ntg = m * 32 + wi * 2 + j;
                    const uint32_t* base = bufB + ktc * 4096 + ntg * 64;
                    uint32_t b0r = base[p0];
                    uint32_t b1r = base[32 + p1];
                    mma_tf32(acc[0][m][j], a0, b0r, b1r);
                    mma_tf32(acc[1][m][j], a1, b0r, b1r);
                }
            }
        }
        if (ch < 7) {
            uint32_t* dstB = smU + OFF_BF + ((ch + 1) & 1) * BUFSTR + dstBase;
#pragma unroll
            for (int p = 0; p < 8; ++p) {
                uint4 c = {f2tf32(pf[p].x), f2tf32(pf[p].y), f2tf32(pf[p].z), f2tf32(pf[p].w)};
                *(uint4*)&dstB[p * 512] = c;
            }
            __syncthreads();
        }
    }
    __syncthreads();   // all fragment reads done; overlays safe

    // ============ Phase B: register epilogue -> z out + phase-C A frags ======
#pragma unroll
    for (int mt = 0; mt < 2; ++mt) {
#pragma unroll
        for (int j = 0; j < 2; ++j) {
            int e2 = cb + j * 8 + 2 * tg;
            float2 bm = *(const float2*)&bmu[e2];
            float2 bs = *(const float2*)&bsig[e2];
            int ktw = wi * 2 + j;
#pragma unroll
            for (int hi = 0; hi < 2; ++hi) {
                int r = mt * 16 + g + 8 * hi;
                int ci = hi * 2;
                float mu0 = acc[mt][0][j][ci + 0] + bm.x;
                float mu1 = acc[mt][0][j][ci + 1] + bm.y;
                float ls0 = acc[mt][1][j][ci + 0] + bs.x;
                float ls1 = acc[mt][1][j][ci + 1] + bs.y;
                float ez0 = __expf(ls0), ez1 = __expf(ls1);
                float2 ep = *(const float2*)&EPS[(b0 + r) * Dd + e2];
                float z0 = fmaf(sqrtf(ez0), ep.x, mu0);
                float z1 = fmaf(sqrtf(ez1), ep.y, mu1);
                float2 zv = {z0, z1};
                *(float2*)&out[(b0 + r) * Dd + e2] = zv;
                float q0 = fmaf(mu0, mu0, ez0);
                float q1 = fmaf(mu1, mu1, ez1);
#pragma unroll
                for (int par = 0; par < 2; ++par) {
                    int dd = 2 * tg + par;
                    int kh = dd >> 2, tgp = dd & 3;
                    int reg = hi + 2 * kh;
                    int lanep = g * 4 + tgp;
                    float zz = par ? z1 : z0;
                    float qq = par ? q1 : q0;
                    float mm = par ? mu1 : mu0;
                    int i1a = OFF_PA1 + ((ktw * 4 + mt)     * 4 + reg) * 32 + lanep;
                    int i1b = OFF_PA1 + ((ktw * 4 + mt + 2) * 4 + reg) * 32 + lanep;
                    int i2a = OFF_PA2 + ((ktw * 4 + mt)     * 4 + reg) * 32 + lanep;
                    int i2b = OFF_PA2 + ((ktw * 4 + mt + 2) * 4 + reg) * 32 + lanep;
                    smU[i1a] = f2tf32(zz * zz);
                    smU[i1b] = f2tf32(qq);
                    smU[i2a] = f2tf32(zz);
                    smU[i2b] = f2tf32(mm);
                }
            }
        }
    }

    // ============ cluster tables -> B frags (+ c2/clsc) ============
    {
        const float4* lsc4 = (const float4*)lsc;
        const float4* muc4 = (const float4*)muc;
#pragma unroll
        for (int p = 0; p < 4; ++p) {
            int j = p * THREADS + t;
            int k = j >> 6, d4 = j & 63;
            float4 l4 = lsc4[j];
            float4 m4 = muc4[j];
            float4 i4 = {__expf(-l4.x), __expf(-l4.y), __expf(-l4.z), __expf(-l4.w)};
            float4 mc = {m4.x * i4.x, m4.y * i4.y, m4.z * i4.z, m4.w * i4.w};
            int kt = d4 >> 1, reg = d4 & 1;
            int g2 = k & 7, ntc = k >> 3;
            int pos = ((kt * 4 + ntc) * 2 + reg) * 32 + ((g2 ^ (kt & 7)) * 4);
            uint4 ci = {f2tf32(i4.x), f2tf32(i4.y), f2tf32(i4.z), f2tf32(i4.w)};
            uint4 cm = {f2tf32(mc.x), f2tf32(mc.y), f2tf32(mc.z), f2tf32(mc.w)};
            *(uint4*)&smU[OFF_ISCF + pos] = ci;
            *(uint4*)&smU[OFF_MCIF + pos] = cm;
            float cp = m4.x * m4.x * i4.x + m4.y * m4.y * i4.y
                     + m4.z * m4.z * i4.z + m4.w * m4.w * i4.w;
            float cl = l4.x + l4.y + l4.z + l4.w;
            cp = wredsum(cp);
            cl = wredsum(cl);
            if (lane == 0) {
                int kk = p * 8 + (wi >> 1);
                int half = wi & 1;
                c2h[kk * 2 + half] = cp;
                clh[kk * 2 + half] = cl;
            }
        }
    }
    __syncthreads();
    if (t < 32) {
        c2f[t] = c2h[t * 2] + c2h[t * 2 + 1];
        clf[t] = clh[t * 2] + clh[t * 2 + 1];
    }
    __syncthreads();

    // ============ Phase C: two 64x32x256 GEMMs on tensor cores ============
    {
        const int mtc = wi >> 2, ntc = wi & 3;
        float dA[2][4];
#pragma unroll
        for (int s = 0; s < 2; ++s)
#pragma unroll
            for (int q = 0; q < 4; ++q) dA[s][q] = 0.f;
#pragma unroll 4
        for (int kt = 0; kt < 32; ++kt) {
            uint32_t af1[4], af2[4];
#pragma unroll
            for (int rr = 0; rr < 4; ++rr) {
                af1[rr] = smU[OFF_PA1 + ((kt * 4 + mtc) * 4 + rr) * 32 + lane];
                af2[rr] = smU[OFF_PA2 + ((kt * 4 + mtc) * 4 + rr) * 32 + lane];
            }
            int lx = lane ^ ((kt & 7) << 2);
            int bb = ((kt * 4 + ntc) * 2) * 32;
            uint32_t i0 = smU[OFF_ISCF + bb + lx];
            uint32_t i1 = smU[OFF_ISCF + bb + 32 + lx];
            uint32_t m0 = smU[OFF_MCIF + bb + lx];
            uint32_t m1 = smU[OFF_MCIF + bb + 32 + lx];
            mma_tf32(dA[0], af1, i0, i1);
            mma_tf32(dA[1], af2, m0, m1);
        }
        // scatter to dots[4][32][33]
        int dot0 = (mtc < 2) ? 0 : 2;
        int rloc = (mtc & 1) * 16 + g;
#pragma unroll
        for (int hi = 0; hi < 2; ++hi) {
#pragma unroll
            for (int par = 0; par < 2; ++par) {
                int r = rloc + 8 * hi;
                int k = ntc * 8 + 2 * tg + par;
                dots[dot0 * 1056 + r * 33 + k]       = dA[0][hi * 2 + par];
                dots[(dot0 + 1) * 1056 + r * 33 + k] = dA[1][hi * 2 + par];
            }
        }
    }
    __syncthreads();

    // ============ softmax + loss partials: warp per 2 rows, lane == k ======
    float c2v = c2f[lane], clv = clf[lane];
    float piAcc = 0.f, gAcc = 0.f;
#pragma unroll
    for (int rr = 0; rr < 2; ++rr) {
        int r = wi * 2 + rr;
        float a1 = dots[0 * 1056 + r * 33 + lane];
        float a2 = dots[1 * 1056 + r * 33 + lane];
        float a3 = dots[2 * 1056 + r * 33 + lane];
        float a4 = dots[3 * 1056 + r * 33 + lane];

        float logit = -(a1 - 2.f * a2 + c2v);
        float S = clv + a3 - 2.f * a4 + c2v;

        float mx = logit;
#pragma unroll
        for (int o = 16; o; o >>= 1) mx = fmaxf(mx, __shfl_xor_sync(0xffffffffu, mx, o));
        float p = __expf(logit - mx);
        float ssum = wredsum(p);
        float pi = p / ssum + 1e-10f;

        piAcc += pi;
        gAcc += wredsum(pi * S);
    }

    // ---- block partials ----
    redPi[wi * 32 + lane] = piAcc;
    if (lane == 0) redG[wi] = gAcc;
    __syncthreads();
    if (wi == 0) {
        float ps = 0.f;
#pragma unroll
        for (int i = 0; i < 16; ++i) ps += redPi[i * 32 + lane];
        g_piPart[blockIdx.x * 32 + lane] = ps;
        if (lane == 0) {
            float gsum = 0.f;
#pragma unroll
            for (int i = 0; i < 16; ++i) gsum += redG[i];
            g_gaussPart[blockIdx.x] = gsum;
        }
    }
    __syncthreads();

    // ---- last-block folded finalize ----
    if (t == 0) {
        __threadfence();
        unsigned int old = atomicAdd(&g_count, 1u);
        *flag = (old == NBLK - 1) ? 1 : 0;
    }
    __syncthreads();
    if (*flag) {
        if (t == 0) atomicExch(&g_count, 0u);
        __threadfence();
        if (t < 256) {
            float gg = g_gaussPart[t];
            gg = wredsum(gg);
            if (lane == 0) redG[wi] = gg;
        }
        {
            float ps = 0.f;
#pragma unroll
            for (int j = 0; j < 16; ++j)
                ps += g_piPart[(wi * 16 + j) * 32 + lane];
            redPi[wi * 32 + lane] = ps;
        }
        __syncthreads();
        if (t == 0) {
            float G = 0.f;
#pragma unroll
            for (int i = 0; i < 8; ++i) G += redG[i];
            out[out_size - 2] = 0.5f * G;
        }
        if (wi == 0) {
            float P = 0.f;
#pragma unroll
            for (int i = 0; i < 16; ++i) P += redPi[i * 32 + lane];
            float mp = P / (float)Bsz;
            float u = mp * logf(mp);
            u = wredsum(u);
            if (lane == 0) out[out_size - 1] = u / (float)Kc;
        }
    }
}

// ---------------------------------------------------------------------------
extern "C" void kernel_launch(void* const* d_in, const int* in_sizes, int n_in,
                              void* d_out, int out_size) {
    const float* X    = (const float*)d_in[0];
    const float* EPS  = (const float*)d_in[1];
    const float* Wmu  = (const float*)d_in[2];
    const float* bmu  = (const float*)d_in[3];
    const float* Wsig = (const float*)d_in[4];
    const float* bsig = (const float*)d_in[5];
    const float* muc  = (const float*)d_in[6];
    const float* lsc  = (const float*)d_in[7];
    float* out = (float*)d_out;

    static bool attr_set = false;
    if (!attr_set) {
        cudaFuncSetAttribute(fused_kernel,
                             cudaFuncAttributeMaxDynamicSharedMemorySize, SMEM_BYTES);
        attr_set = true;
    }
    fused_kernel<<<NBLK, THREADS, SMEM_BYTES>>>(X, EPS, Wmu, bmu, Wsig, bsig,
                                                muc, lsc, out, out_size);
}